// round 1
// baseline (speedup 1.0000x reference)
#include <cuda_runtime.h>
#include <math.h>

// Problem constants
#define BB 8
#define DD 4096
#define NPROJ 12288      // 3*D
#define SS 16
#define FFD 16384
#define FIR_OFF 32768            // d_out offset of new_fir  (B*D elems of x first)
#define IIR_OFF 229376           // 32768 + 196608

// ---------------- scratch (__device__ globals; no allocation allowed) -------
__device__ float g_xn1 [BB*DD];
__device__ float g_y   [BB*DD];
__device__ float g_xnew[BB*DD];
__device__ float g_xn2 [BB*DD];
__device__ float g_g   [BB*FFD];
__device__ float g_ssq [BB];
__device__ float g_pA  [2097152];   // split-K partials (max 2.1M floats)
__device__ float g_pB  [2097152];

// ---------------- rmsnorm of input x ----------------------------------------
__global__ void rmsnorm1_kernel(const float* __restrict__ x,
                                const float* __restrict__ w,
                                float* __restrict__ out) {
    int b = blockIdx.x;          // 8 blocks
    int tid = threadIdx.x;       // 512 threads
    float v[8];
    float ss = 0.f;
#pragma unroll
    for (int e = 0; e < 8; e++) {
        float t = x[b*DD + e*512 + tid];
        v[e] = t; ss += t*t;
    }
    __shared__ float red[16];
    int lane = tid & 31, wid = tid >> 5;
#pragma unroll
    for (int o = 16; o; o >>= 1) ss += __shfl_xor_sync(0xffffffffu, ss, o);
    if (lane == 0) red[wid] = ss;
    __syncthreads();
    if (tid == 0) { float t = 0.f; for (int i = 0; i < 16; i++) t += red[i]; red[0] = t; }
    __syncthreads();
    float scale = rsqrtf(red[0] * (1.f/DD) + 1e-6f);
#pragma unroll
    for (int e = 0; e < 8; e++)
        out[b*DD + e*512 + tid] = v[e] * scale * w[e*512 + tid];
}

// ---------------- split-K GEMV: P[chunk][b][n] = sum_{k in chunk} X[b][k]*W[k][n]
template<int KCH>
__global__ void gemv_partial(const float* __restrict__ W,
                             const float* __restrict__ X,
                             float* __restrict__ P, int K, int N) {
    __shared__ float xs[8*KCH];
    int tid = threadIdx.x;                 // 128 threads
    int k0  = blockIdx.y * KCH;
#pragma unroll
    for (int i = tid; i < 8*KCH; i += 128) {
        int b = i / KCH, k = i % KCH;
        xs[i] = X[b*K + k0 + k];
    }
    __syncthreads();
    int Nv = N >> 2;
    int col4 = blockIdx.x*128 + tid;       // float4 column index
    const float4* Wv = reinterpret_cast<const float4*>(W) + (size_t)k0*Nv + col4;
    float4 acc[8];
#pragma unroll
    for (int b = 0; b < 8; b++) acc[b] = make_float4(0.f,0.f,0.f,0.f);
#pragma unroll 8
    for (int k = 0; k < KCH; k++) {
        float4 w = Wv[(size_t)k * Nv];
#pragma unroll
        for (int b = 0; b < 8; b++) {
            float xv = xs[b*KCH + k];
            acc[b].x = fmaf(w.x, xv, acc[b].x);
            acc[b].y = fmaf(w.y, xv, acc[b].y);
            acc[b].z = fmaf(w.z, xv, acc[b].z);
            acc[b].w = fmaf(w.w, xv, acc[b].w);
        }
    }
    float4* Pv = reinterpret_cast<float4*>(P) + (size_t)blockIdx.y*(2*N) + col4;
#pragma unroll
    for (int b = 0; b < 8; b++) Pv[b*Nv] = acc[b];
}

// ---------------- FIR + gating split + IIR (reduces proj partials, 16 chunks)
__global__ void fir_iir_kernel(const float* __restrict__ P,
                               const float* __restrict__ fir_state,
                               const float* __restrict__ sfw,
                               const float* __restrict__ sfb,
                               const float* __restrict__ iir,
                               const float* __restrict__ lp,
                               const float* __restrict__ resid,
                               const float* __restrict__ Dres,
                               float* __restrict__ y,
                               float* __restrict__ dout) {
    int blk = blockIdx.x;                // 256 blocks = 8 batch * 32 heads
    int b = blk >> 5, h = blk & 31;
    int j = threadIdx.x;                 // 128 threads = DPH
    if (blk == 0 && j < BB) g_ssq[j] = 0.f;   // pre-zero for reduce_res

    float zp[3];
#pragma unroll
    for (int e = 0; e < 3; e++) {
        int i  = h*384 + e*128 + j;
        int gi = b*NPROJ + i;
        float u = 0.f;
#pragma unroll
        for (int c = 0; c < 16; c++) u += P[c*(8*NPROJ) + gi];
        float f0 = fir_state[gi*2 + 0];
        float f1 = fir_state[gi*2 + 1];
        float w0 = sfw[i*3 + 0], w1 = sfw[i*3 + 1], w2 = sfw[i*3 + 2];
        zp[e] = w2*u + f0*w0 + f1*w1 + sfb[i];
        dout[FIR_OFF + gi*2 + 0] = f1;   // new_fir = [f1, u]
        dout[FIR_OFF + gi*2 + 1] = u;
    }
    int d = h*128 + j;
    float x2 = zp[0], x1 = zp[1], v = zp[2];
    float x1v = x1 * v;
    float res = 0.f;
    int base = (b*DD + d)*SS;
#pragma unroll
    for (int s = 0; s < SS; s++) {
        float pole = expf(lp[d*SS + s]);
        float ni = fmaf(pole, iir[base + s], x1v);
        dout[IIR_OFF + base + s] = ni;
        res = fmaf(resid[d*SS + s], ni, res);
    }
    y[b*DD + d] = x2 * (res + Dres[d]*x1v);
}

// ---------------- reduce out_w partials (32 chunks) + bias + residual + ssq --
__global__ void reduce_res_kernel(const float* __restrict__ P,
                                  const float* __restrict__ x,
                                  const float* __restrict__ ob,
                                  float* __restrict__ xnew) {
    int gid = blockIdx.x*256 + threadIdx.x;    // 32768 total
    int b = gid >> 12, n = gid & (DD-1);
    float v = x[gid] + ob[n];
#pragma unroll
    for (int c = 0; c < 32; c++) v += P[c*(8*DD) + gid];
    xnew[gid] = v;
    float ss = v*v;
#pragma unroll
    for (int o = 16; o; o >>= 1) ss += __shfl_xor_sync(0xffffffffu, ss, o);
    __shared__ float red[8];
    int lane = threadIdx.x & 31, wid = threadIdx.x >> 5;
    if (lane == 0) red[wid] = ss;
    __syncthreads();
    if (threadIdx.x == 0) {
        float t = 0.f;
        for (int i = 0; i < 8; i++) t += red[i];
        atomicAdd(&g_ssq[b], t);
    }
}

// ---------------- post-norm scale -------------------------------------------
__global__ void scale_kernel(const float* __restrict__ xnew,
                             const float* __restrict__ w,
                             float* __restrict__ xn2) {
    int gid = blockIdx.x*256 + threadIdx.x;
    int b = gid >> 12, n = gid & (DD-1);
    xn2[gid] = xnew[gid] * rsqrtf(g_ssq[b]*(1.f/DD) + 1e-6f) * w[n];
}

// ---------------- SwiGLU: g = silu(sum pA) * (sum pB)  (16 chunks each) ------
__global__ void glu_kernel(const float* __restrict__ PA,
                           const float* __restrict__ PB,
                           float* __restrict__ g) {
    int gid = blockIdx.x*256 + threadIdx.x;    // 131072 total
    float a = 0.f, c3 = 0.f;
#pragma unroll
    for (int c = 0; c < 16; c++) {
        a  += PA[c*(8*FFD) + gid];
        c3 += PB[c*(8*FFD) + gid];
    }
    g[gid] = (a / (1.f + expf(-a))) * c3;
}

// ---------------- final: x_out = xnew + reduce64(mlp_w2 partials) ------------
__global__ void final_kernel(const float* __restrict__ P,
                             const float* __restrict__ xnew,
                             float* __restrict__ dout) {
    int gid = blockIdx.x*256 + threadIdx.x;    // 32768 total
    float v = xnew[gid];
#pragma unroll
    for (int c = 0; c < 64; c++) v += P[c*(8*DD) + gid];
    dout[gid] = v;
}

// ---------------- host launcher ----------------------------------------------
extern "C" void kernel_launch(void* const* d_in, const int* in_sizes, int n_in,
                              void* d_out, int out_size) {
    (void)in_sizes; (void)n_in; (void)out_size;
    const float* x          = (const float*)d_in[0];
    const float* fir_state  = (const float*)d_in[1];
    const float* iir_state  = (const float*)d_in[2];
    const float* pre_w      = (const float*)d_in[3];
    const float* proj_w     = (const float*)d_in[4];
    const float* sfw        = (const float*)d_in[5];
    const float* sfb        = (const float*)d_in[6];
    const float* Dres       = (const float*)d_in[7];
    const float* resid      = (const float*)d_in[8];
    const float* lp         = (const float*)d_in[9];
    const float* out_w      = (const float*)d_in[10];
    const float* out_b      = (const float*)d_in[11];
    const float* post_w     = (const float*)d_in[12];
    const float* w1         = (const float*)d_in[13];
    const float* w3         = (const float*)d_in[14];
    const float* w2         = (const float*)d_in[15];
    float* out = (float*)d_out;

    float *xn1, *y, *xnew, *xn2, *g, *pA, *pB;
    cudaGetSymbolAddress((void**)&xn1,  g_xn1);
    cudaGetSymbolAddress((void**)&y,    g_y);
    cudaGetSymbolAddress((void**)&xnew, g_xnew);
    cudaGetSymbolAddress((void**)&xn2,  g_xn2);
    cudaGetSymbolAddress((void**)&g,    g_g);
    cudaGetSymbolAddress((void**)&pA,   g_pA);
    cudaGetSymbolAddress((void**)&pB,   g_pB);

    // 1. pre-norm
    rmsnorm1_kernel<<<BB, 512>>>(x, pre_w, xn1);
    // 2. z = xn1 @ proj_w  (4096 x 12288), KCH=256 -> 16 chunks, 384 blocks
    gemv_partial<256><<<dim3(24,16), 128>>>(proj_w, xn1, pA, DD, NPROJ);
    // 3. FIR + split + IIR  -> y, new_fir, new_iir (also zeroes g_ssq)
    fir_iir_kernel<<<256, 128>>>(pA, fir_state, sfw, sfb, iir_state, lp, resid, Dres, y, out);
    // 4. y @ out_w (4096 x 4096), KCH=128 -> 32 chunks, 256 blocks
    gemv_partial<128><<<dim3(8,32), 128>>>(out_w, y, pA, DD, DD);
    // 5. xnew = reduce + out_b + x; accumulate sum of squares
    reduce_res_kernel<<<128, 256>>>(pA, x, out_b, xnew);
    // 6. xn2 = rmsnorm(xnew) * post_w
    scale_kernel<<<128, 256>>>(xnew, post_w, xn2);
    // 7/8. MLP up-projections (4096 x 16384), KCH=256 -> 16 chunks, 512 blocks each
    gemv_partial<256><<<dim3(32,16), 128>>>(w1, xn2, pA, DD, FFD);
    gemv_partial<256><<<dim3(32,16), 128>>>(w3, xn2, pB, DD, FFD);
    // 9. SwiGLU gate
    glu_kernel<<<512, 256>>>(pA, pB, g);
    // 10. g @ mlp_w2 (16384 x 4096), KCH=256 -> 64 chunks, 512 blocks
    gemv_partial<256><<<dim3(8,64), 128>>>(w2, g, pA, FFD, DD);
    // 11. x_out = xnew + reduce
    final_kernel<<<128, 256>>>(pA, xnew, out);
}

// round 2
// speedup vs baseline: 1.7863x; 1.7863x over previous
#include <cuda_runtime.h>
#include <math.h>

// Problem constants
#define BB 8
#define DD 4096
#define NPROJ 12288      // 3*D
#define SS 16
#define FFD 16384
#define FIR_OFF 32768            // d_out offset of new_fir  (B*D elems of x first)
#define IIR_OFF 229376           // 32768 + 196608

typedef unsigned long long ull;

// ---------------- scratch (__device__ globals; no allocation allowed) -------
__device__ float g_xn1 [BB*DD];
__device__ float g_y   [BB*DD];
__device__ float g_xnew[BB*DD];
__device__ float g_xn2 [BB*DD];
__device__ float g_g   [BB*FFD];
__device__ float g_ssq [BB];
__device__ float g_pA  [2097152];   // split-K partials
__device__ float g_pB  [2097152];

__device__ __forceinline__ void fma2(ull& a, ull w, ull x) {
    asm("fma.rn.f32x2 %0, %1, %2, %0;" : "+l"(a) : "l"(w), "l"(x));
}

// ---------------- rmsnorm of input x ----------------------------------------
__global__ void rmsnorm1_kernel(const float* __restrict__ x,
                                const float* __restrict__ w,
                                float* __restrict__ out) {
    int b = blockIdx.x;          // 8 blocks
    int tid = threadIdx.x;       // 512 threads
    float v[8];
    float ss = 0.f;
#pragma unroll
    for (int e = 0; e < 8; e++) {
        float t = x[b*DD + e*512 + tid];
        v[e] = t; ss += t*t;
    }
    __shared__ float red[16];
    int lane = tid & 31, wid = tid >> 5;
#pragma unroll
    for (int o = 16; o; o >>= 1) ss += __shfl_xor_sync(0xffffffffu, ss, o);
    if (lane == 0) red[wid] = ss;
    __syncthreads();
    if (tid == 0) { float t = 0.f; for (int i = 0; i < 16; i++) t += red[i]; red[0] = t; }
    __syncthreads();
    float scale = rsqrtf(red[0] * (1.f/DD) + 1e-6f);
#pragma unroll
    for (int e = 0; e < 8; e++)
        out[b*DD + e*512 + tid] = v[e] * scale * w[e*512 + tid];
}

// ---------------- split-K GEMV with batched loads + f32x2 FMA ---------------
// P[chunk][b][n] = sum_{k in chunk} X[b][k] * W[k][n]
template<int KCH>
__global__ __launch_bounds__(256, 2)
void gemv_partial(const float* __restrict__ W,
                  const float* __restrict__ X,
                  float* __restrict__ P, int K, int N) {
    __shared__ float2 xs2[8*KCH];        // activation duplicated (x,x) for LDS.64
    int tid = threadIdx.x;               // 256 threads
    int k0  = blockIdx.y * KCH;
#pragma unroll
    for (int i = tid; i < 8*KCH; i += 256) {
        int b = i / KCH, k = i % KCH;
        float v = X[b*K + k0 + k];
        xs2[i] = make_float2(v, v);
    }
    __syncthreads();

    int Nv = N >> 2;                     // float4 columns
    int col4 = blockIdx.x*256 + tid;
    const ulonglong2* Wv = reinterpret_cast<const ulonglong2*>(W)
                         + (size_t)k0*Nv + col4;
    ull acc[8][2];
#pragma unroll
    for (int b = 0; b < 8; b++) { acc[b][0] = 0ull; acc[b][1] = 0ull; }

#pragma unroll 1
    for (int k = 0; k < KCH; k += 16) {
        ulonglong2 wv[16];
#pragma unroll
        for (int i = 0; i < 16; i++)     // 16 LDG.128 issued back-to-back
            wv[i] = Wv[(size_t)(k+i)*Nv];
#pragma unroll
        for (int i = 0; i < 16; i++) {
#pragma unroll
            for (int b = 0; b < 8; b++) {
                ull xx = *reinterpret_cast<const ull*>(&xs2[b*KCH + k + i]);
                fma2(acc[b][0], wv[i].x, xx);
                fma2(acc[b][1], wv[i].y, xx);
            }
        }
    }

    ulonglong2* Pv = reinterpret_cast<ulonglong2*>(P)
                   + (size_t)blockIdx.y*(N<<1) + col4;
#pragma unroll
    for (int b = 0; b < 8; b++)
        Pv[(size_t)b*Nv] = make_ulonglong2(acc[b][0], acc[b][1]);
}

// ---------------- FIR + gating split + IIR (reduces proj partials, 16 chunks)
__global__ void fir_iir_kernel(const float* __restrict__ P,
                               const float* __restrict__ fir_state,
                               const float* __restrict__ sfw,
                               const float* __restrict__ sfb,
                               const float* __restrict__ iir,
                               const float* __restrict__ lp,
                               const float* __restrict__ resid,
                               const float* __restrict__ Dres,
                               float* __restrict__ y,
                               float* __restrict__ dout) {
    int blk = blockIdx.x;                // 256 blocks = 8 batch * 32 heads
    int b = blk >> 5, h = blk & 31;
    int j = threadIdx.x;                 // 128 threads = DPH
    if (blk == 0 && j < BB) g_ssq[j] = 0.f;   // pre-zero for reduce_res

    float zp[3];
#pragma unroll
    for (int e = 0; e < 3; e++) {
        int i  = h*384 + e*128 + j;
        int gi = b*NPROJ + i;
        float u = 0.f;
#pragma unroll
        for (int c = 0; c < 16; c++) u += P[c*(8*NPROJ) + gi];
        float f0 = fir_state[gi*2 + 0];
        float f1 = fir_state[gi*2 + 1];
        float w0 = sfw[i*3 + 0], w1 = sfw[i*3 + 1], w2 = sfw[i*3 + 2];
        zp[e] = w2*u + f0*w0 + f1*w1 + sfb[i];
        dout[FIR_OFF + gi*2 + 0] = f1;   // new_fir = [f1, u]
        dout[FIR_OFF + gi*2 + 1] = u;
    }
    int d = h*128 + j;
    float x2 = zp[0], x1 = zp[1], v = zp[2];
    float x1v = x1 * v;
    float res = 0.f;
    int base = (b*DD + d)*SS;
#pragma unroll
    for (int s = 0; s < SS; s++) {
        float pole = expf(lp[d*SS + s]);
        float ni = fmaf(pole, iir[base + s], x1v);
        dout[IIR_OFF + base + s] = ni;
        res = fmaf(resid[d*SS + s], ni, res);
    }
    y[b*DD + d] = x2 * (res + Dres[d]*x1v);
}

// ---------------- reduce out_w partials (64 chunks) + bias + residual + ssq --
__global__ void reduce_res_kernel(const float4* __restrict__ P4,
                                  const float4* __restrict__ x4,
                                  const float4* __restrict__ ob4,
                                  float4* __restrict__ xnew4) {
    int g4 = blockIdx.x*256 + threadIdx.x;    // 8192 float4 total, 32 blocks
    int b = g4 >> 10, n4 = g4 & 1023;
    float4 v = x4[g4], o = ob4[n4];
    v.x += o.x; v.y += o.y; v.z += o.z; v.w += o.w;
#pragma unroll
    for (int c = 0; c < 64; c++) {
        float4 p = P4[c*8192 + g4];
        v.x += p.x; v.y += p.y; v.z += p.z; v.w += p.w;
    }
    xnew4[g4] = v;
    float ss = v.x*v.x + v.y*v.y + v.z*v.z + v.w*v.w;
#pragma unroll
    for (int o2 = 16; o2; o2 >>= 1) ss += __shfl_xor_sync(0xffffffffu, ss, o2);
    __shared__ float red[8];
    int lane = threadIdx.x & 31, wid = threadIdx.x >> 5;
    if (lane == 0) red[wid] = ss;
    __syncthreads();
    if (threadIdx.x == 0) {
        float t = 0.f;
        for (int i = 0; i < 8; i++) t += red[i];
        atomicAdd(&g_ssq[b], t);
    }
}

// ---------------- post-norm scale -------------------------------------------
__global__ void scale_kernel(const float* __restrict__ xnew,
                             const float* __restrict__ w,
                             float* __restrict__ xn2) {
    int gid = blockIdx.x*256 + threadIdx.x;
    int b = gid >> 12, n = gid & (DD-1);
    xn2[gid] = xnew[gid] * rsqrtf(g_ssq[b]*(1.f/DD) + 1e-6f) * w[n];
}

// ---------------- SwiGLU: g = silu(sum pA) * (sum pB)  (16 chunks each) ------
__global__ void glu_kernel(const float4* __restrict__ PA4,
                           const float4* __restrict__ PB4,
                           float4* __restrict__ g4out) {
    int g4 = blockIdx.x*256 + threadIdx.x;    // 32768 float4, 128 blocks
    float4 a = make_float4(0,0,0,0), c3 = make_float4(0,0,0,0);
#pragma unroll
    for (int c = 0; c < 16; c++) {
        float4 pa = PA4[c*32768 + g4];
        float4 pb = PB4[c*32768 + g4];
        a.x += pa.x; a.y += pa.y; a.z += pa.z; a.w += pa.w;
        c3.x += pb.x; c3.y += pb.y; c3.z += pb.z; c3.w += pb.w;
    }
    float4 r;
    r.x = (a.x / (1.f + expf(-a.x))) * c3.x;
    r.y = (a.y / (1.f + expf(-a.y))) * c3.y;
    r.z = (a.z / (1.f + expf(-a.z))) * c3.z;
    r.w = (a.w / (1.f + expf(-a.w))) * c3.w;
    g4out[g4] = r;
}

// ---------------- final: x_out = xnew + reduce64(mlp_w2 partials) ------------
__global__ void final_kernel(const float4* __restrict__ P4,
                             const float4* __restrict__ xnew4,
                             float4* __restrict__ dout4) {
    int g4 = blockIdx.x*256 + threadIdx.x;    // 8192 float4, 32 blocks
    float4 v = xnew4[g4];
#pragma unroll
    for (int c = 0; c < 64; c++) {
        float4 p = P4[c*8192 + g4];
        v.x += p.x; v.y += p.y; v.z += p.z; v.w += p.w;
    }
    dout4[g4] = v;
}

// ---------------- host launcher ----------------------------------------------
extern "C" void kernel_launch(void* const* d_in, const int* in_sizes, int n_in,
                              void* d_out, int out_size) {
    (void)in_sizes; (void)n_in; (void)out_size;
    const float* x          = (const float*)d_in[0];
    const float* fir_state  = (const float*)d_in[1];
    const float* iir_state  = (const float*)d_in[2];
    const float* pre_w      = (const float*)d_in[3];
    const float* proj_w     = (const float*)d_in[4];
    const float* sfw        = (const float*)d_in[5];
    const float* sfb        = (const float*)d_in[6];
    const float* Dres       = (const float*)d_in[7];
    const float* resid      = (const float*)d_in[8];
    const float* lp         = (const float*)d_in[9];
    const float* out_w      = (const float*)d_in[10];
    const float* out_b      = (const float*)d_in[11];
    const float* post_w     = (const float*)d_in[12];
    const float* w1         = (const float*)d_in[13];
    const float* w3         = (const float*)d_in[14];
    const float* w2         = (const float*)d_in[15];
    float* out = (float*)d_out;

    float *xn1, *y, *xnew, *xn2, *g, *pA, *pB;
    cudaGetSymbolAddress((void**)&xn1,  g_xn1);
    cudaGetSymbolAddress((void**)&y,    g_y);
    cudaGetSymbolAddress((void**)&xnew, g_xnew);
    cudaGetSymbolAddress((void**)&xn2,  g_xn2);
    cudaGetSymbolAddress((void**)&g,    g_g);
    cudaGetSymbolAddress((void**)&pA,   g_pA);
    cudaGetSymbolAddress((void**)&pB,   g_pB);

    // 1. pre-norm
    rmsnorm1_kernel<<<BB, 512>>>(x, pre_w, xn1);
    // 2. z = xn1 @ proj_w (4096x12288): 12 col-blocks x 16 chunks = 192 blocks
    gemv_partial<256><<<dim3(12,16), 256>>>(proj_w, xn1, pA, DD, NPROJ);
    // 3. FIR + split + IIR -> y, new_fir, new_iir (also zeroes g_ssq)
    fir_iir_kernel<<<256, 128>>>(pA, fir_state, sfw, sfb, iir_state, lp, resid, Dres, y, out);
    // 4. y @ out_w (4096x4096): 4 col-blocks x 64 chunks = 256 blocks
    gemv_partial<64><<<dim3(4,64), 256>>>(out_w, y, pA, DD, DD);
    // 5. xnew = reduce + out_b + x; accumulate sum of squares
    reduce_res_kernel<<<32, 256>>>((const float4*)pA, (const float4*)x,
                                   (const float4*)out_b, (float4*)xnew);
    // 6. xn2 = rmsnorm(xnew) * post_w
    scale_kernel<<<128, 256>>>(xnew, post_w, xn2);
    // 7/8. MLP up (4096x16384): 16 col-blocks x 16 chunks = 256 blocks each
    gemv_partial<256><<<dim3(16,16), 256>>>(w1, xn2, pA, DD, FFD);
    gemv_partial<256><<<dim3(16,16), 256>>>(w3, xn2, pB, DD, FFD);
    // 9. SwiGLU gate
    glu_kernel<<<128, 256>>>((const float4*)pA, (const float4*)pB, (float4*)g);
    // 10. g @ mlp_w2 (16384x4096): 4 col-blocks x 64 chunks = 256 blocks
    gemv_partial<256><<<dim3(4,64), 256>>>(w2, g, pA, FFD, DD);
    // 11. x_out = xnew + reduce
    final_kernel<<<32, 256>>>((const float4*)pA, (const float4*)xnew, (float4*)out);
}